// round 4
// baseline (speedup 1.0000x reference)
#include <cuda_runtime.h>
#include <cstdint>

#define N_NODES  100000
#define D_MODEL  128
#define N_EDGES  1600000
#define HEADS    8
#define DHEAD    16

// ---------------- device scratch (no allocations allowed) ----------------
__device__ float g_q[N_NODES * D_MODEL];
__device__ float g_k[N_NODES * D_MODEL];
__device__ float g_v[N_NODES * D_MODEL];
__device__ float g_smax[N_NODES * HEADS];
__device__ float g_ssum[N_NODES * HEADS];
__device__ float g_masked[(size_t)N_EDGES * HEADS];

// float atomic max via sign-split int/uint atomics (valid with -inf init)
__device__ __forceinline__ void atomicMaxF(float* addr, float v) {
    if (v >= 0.f) atomicMax((int*)addr, __float_as_int(v));
    else          atomicMin((unsigned int*)addr, __float_as_uint(v));
}

// ---------------- init: zero node_states output, init smax/ssum ----------------
__global__ void init_kernel(float* __restrict__ node_out, int n) {
    int idx = blockIdx.x * blockDim.x + threadIdx.x;
    int tot = n * D_MODEL;
    if (idx < tot) node_out[idx] = 0.f;
    if (idx < n * HEADS) {
        g_smax[idx] = __int_as_float(0xff800000);  // -inf
        g_ssum[idx] = 0.f;
    }
}

// ---------------- fused QKV GEMM: C[n,384] = x[n,128] @ [Wq|Wk|Wv] + bias ----------------
// 64x64 tile, BK=64, 256 threads, 4x4 register micro-tile per thread.
__global__ __launch_bounds__(256) void qkv_gemm_kernel(
    const float* __restrict__ x,
    const float* __restrict__ Wq, const float* __restrict__ bq,
    const float* __restrict__ Wk, const float* __restrict__ bk,
    const float* __restrict__ Wv, const float* __restrict__ bv,
    int n)
{
    __shared__ float As[64][65];  // [k][m], pad to dodge store conflicts
    __shared__ float Bs[64][64];  // [k][c]

    const int tid = threadIdx.x;
    const int bm  = blockIdx.x * 64;
    const int sel = blockIdx.y >> 1;        // 0=Q 1=K 2=V
    const int bn  = (blockIdx.y & 1) * 64;  // column half within the 128-wide matrix

    const float* W    = (sel == 0) ? Wq : (sel == 1 ? Wk : Wv);
    const float* bias = (sel == 0) ? bq : (sel == 1 ? bk : bv);
    float* Out        = (sel == 0) ? g_q : (sel == 1 ? g_k : g_v);

    const int tx = tid & 15;   // col group
    const int ty = tid >> 4;   // row group

    float acc[4][4];
#pragma unroll
    for (int i = 0; i < 4; i++)
#pragma unroll
        for (int j = 0; j < 4; j++) acc[i][j] = 0.f;

    for (int kk = 0; kk < 128; kk += 64) {
        // load A tile (64 rows x 64 k), transpose into k-major smem
#pragma unroll
        for (int j = 0; j < 4; j++) {
            int i   = tid + j * 256;
            int row = i >> 4;
            int kc  = (i & 15) << 2;
            float4 a = make_float4(0.f, 0.f, 0.f, 0.f);
            if (bm + row < n)
                a = *(const float4*)(x + (size_t)(bm + row) * 128 + kk + kc);
            As[kc + 0][row] = a.x;
            As[kc + 1][row] = a.y;
            As[kc + 2][row] = a.z;
            As[kc + 3][row] = a.w;
        }
        // load B tile (64 k x 64 cols)
#pragma unroll
        for (int j = 0; j < 4; j++) {
            int i  = tid + j * 256;
            int k  = i >> 4;
            int cc = (i & 15) << 2;
            *(float4*)&Bs[k][cc] = *(const float4*)(W + (size_t)(kk + k) * 128 + bn + cc);
        }
        __syncthreads();

#pragma unroll 8
        for (int k = 0; k < 64; k++) {
            float a0 = As[k][ty * 4 + 0];
            float a1 = As[k][ty * 4 + 1];
            float a2 = As[k][ty * 4 + 2];
            float a3 = As[k][ty * 4 + 3];
            float4 b = *(const float4*)&Bs[k][tx * 4];
            acc[0][0] += a0 * b.x; acc[0][1] += a0 * b.y; acc[0][2] += a0 * b.z; acc[0][3] += a0 * b.w;
            acc[1][0] += a1 * b.x; acc[1][1] += a1 * b.y; acc[1][2] += a1 * b.z; acc[1][3] += a1 * b.w;
            acc[2][0] += a2 * b.x; acc[2][1] += a2 * b.y; acc[2][2] += a2 * b.z; acc[2][3] += a2 * b.w;
            acc[3][0] += a3 * b.x; acc[3][1] += a3 * b.y; acc[3][2] += a3 * b.z; acc[3][3] += a3 * b.w;
        }
        __syncthreads();
    }

    float4 bb = *(const float4*)(bias + bn + tx * 4);
#pragma unroll
    for (int i = 0; i < 4; i++) {
        int row = bm + ty * 4 + i;
        if (row < n) {
            float4 o;
            o.x = acc[i][0] + bb.x;
            o.y = acc[i][1] + bb.y;
            o.z = acc[i][2] + bb.z;
            o.w = acc[i][3] + bb.w;
            *(float4*)(Out + (size_t)row * 128 + bn + tx * 4) = o;
        }
    }
}

// ---------------- pass 1: per-edge scores + segment max (warp per edge) ----------------
__global__ __launch_bounds__(256) void edge_scores_kernel(
    const float* __restrict__ pi, const float* __restrict__ vw,
    const int* __restrict__ src, const int* __restrict__ dst, int E)
{
    int warp = (int)((blockIdx.x * (unsigned)blockDim.x + threadIdx.x) >> 5);
    int lane = threadIdx.x & 31;
    if (warp >= E) return;
    int s = src[warp];
    int d = dst[warp];

    float4 q4 = *(const float4*)(g_q + (size_t)d * 128 + lane * 4);
    float4 k4 = *(const float4*)(g_k + (size_t)s * 128 + lane * 4);
    float p = q4.x * k4.x + q4.y * k4.y + q4.z * k4.z + q4.w * k4.w;
    p += __shfl_xor_sync(0xffffffffu, p, 1);
    p += __shfl_xor_sync(0xffffffffu, p, 2);
    // lanes 4h..4h+3 now all hold raw dot for head h = lane>>2

    if ((lane & 3) == 0) {
        int h = lane >> 2;
        float mix = 0.f;
#pragma unroll
        for (int m = 0; m < 3; m++)
            mix += pi[(size_t)d * 24 + h * 3 + m] * vw[(size_t)warp * 3 + m];
        float score;
        if (mix > 0.f) score = p * 0.25f + logf(fmaxf(mix, 1e-8f));
        else           score = -1e9f;
        g_masked[(size_t)warp * 8 + h] = score;
        atomicMaxF(&g_smax[(size_t)d * 8 + h], score);
    }
}

// ---------------- pass 2: exp and segment sum (thread per edge-head) ----------------
__global__ __launch_bounds__(256) void edge_exp_kernel(
    const int* __restrict__ dst, float* __restrict__ attn_out, int E)
{
    int idx = blockIdx.x * blockDim.x + threadIdx.x;
    if (idx >= E * HEADS) return;
    int e = idx >> 3;
    int h = idx & 7;
    int d = dst[e];
    float m  = g_masked[idx];
    float ex = 0.f;
    if (m > -1e8f) ex = expf(m - g_smax[(size_t)d * 8 + h]);
    attn_out[idx] = ex;
    if (ex != 0.f) atomicAdd(&g_ssum[(size_t)d * 8 + h], ex);
}

// ---------------- pass 3: normalize attn + weighted scatter of V (warp per edge) ----------------
__global__ __launch_bounds__(256) void edge_aggregate_kernel(
    const int* __restrict__ src, const int* __restrict__ dst,
    float* __restrict__ attn, float* __restrict__ node_out, int E)
{
    int warp = (int)((blockIdx.x * (unsigned)blockDim.x + threadIdx.x) >> 5);
    int lane = threadIdx.x & 31;
    if (warp >= E) return;
    int s = src[warp];
    int d = dst[warp];

    float a = 0.f;
    if (lane < 8) {
        float ex = attn[(size_t)warp * 8 + lane];
        float ss = g_ssum[(size_t)d * 8 + lane];
        a = ex / fmaxf(ss, 1e-8f);
        attn[(size_t)warp * 8 + lane] = a;
    }
    // lane l needs attn of head l>>2, held by lane (l>>2)
    float ah = __shfl_sync(0xffffffffu, a, lane >> 2);

    float4 v4 = *(const float4*)(g_v + (size_t)s * 128 + lane * 4);
    float* dp = node_out + (size_t)d * 128 + lane * 4;
    asm volatile("red.global.add.v4.f32 [%0], {%1, %2, %3, %4};"
                 :: "l"(dp), "f"(v4.x * ah), "f"(v4.y * ah), "f"(v4.z * ah), "f"(v4.w * ah)
                 : "memory");
}

// ---------------- launch ----------------
extern "C" void kernel_launch(void* const* d_in, const int* in_sizes, int n_in,
                              void* d_out, int out_size)
{
    const float* x  = (const float*)d_in[0];
    const float* pi = (const float*)d_in[1];
    const float* vw = (const float*)d_in[2];
    const float* Wq = (const float*)d_in[3];
    const float* bq = (const float*)d_in[4];
    const float* Wk = (const float*)d_in[5];
    const float* bk = (const float*)d_in[6];
    const float* Wv = (const float*)d_in[7];
    const float* bv = (const float*)d_in[8];
    const int* src  = (const int*)d_in[9];
    const int* dst  = (const int*)d_in[10];

    int n = in_sizes[0] / D_MODEL;
    int E = in_sizes[9];

    float* out_ns   = (float*)d_out;                    // [n, H, DH] = [n,128]
    float* out_attn = out_ns + (size_t)n * D_MODEL;     // [E, H]

    init_kernel<<<(n * D_MODEL + 255) / 256, 256>>>(out_ns, n);
    qkv_gemm_kernel<<<dim3((n + 63) / 64, 6), 256>>>(x, Wq, bq, Wk, bk, Wv, bv, n);
    edge_scores_kernel<<<(E + 7) / 8, 256>>>(pi, vw, src, dst, E);
    edge_exp_kernel<<<(E * HEADS + 255) / 256, 256>>>(dst, out_attn, E);
    edge_aggregate_kernel<<<(E + 7) / 8, 256>>>(src, dst, out_attn, out_ns, E);
}

// round 5
// speedup vs baseline: 1.4048x; 1.4048x over previous
#include <cuda_runtime.h>
#include <cstdint>

#define N_NODES  100000
#define D_MODEL  128
#define N_EDGES  1600000
#define HEADS    8
#define DHEAD    16

// ---------------- device scratch (no allocations allowed) ----------------
__device__ float g_q[N_NODES * D_MODEL];
__device__ float g_k[N_NODES * D_MODEL];
__device__ float g_v[N_NODES * D_MODEL];
__device__ float g_ssum[N_NODES * HEADS];

// ---------------- init: zero node_states output + ssum ----------------
__global__ void init_kernel(float* __restrict__ node_out, int n) {
    int idx = blockIdx.x * blockDim.x + threadIdx.x;
    if (idx < n * D_MODEL) node_out[idx] = 0.f;
    if (idx < n * HEADS)   g_ssum[idx] = 0.f;
}

// ---------------- fused QKV GEMM: C[n,384] = x[n,128] @ [Wq|Wk|Wv] + bias ----------------
// 64x64 tile, BK=64, 256 threads, 4x4 register micro-tile per thread.
__global__ __launch_bounds__(256) void qkv_gemm_kernel(
    const float* __restrict__ x,
    const float* __restrict__ Wq, const float* __restrict__ bq,
    const float* __restrict__ Wk, const float* __restrict__ bk,
    const float* __restrict__ Wv, const float* __restrict__ bv,
    int n)
{
    __shared__ float As[64][65];  // [k][m], pad to dodge store conflicts
    __shared__ float Bs[64][64];  // [k][c]

    const int tid = threadIdx.x;
    const int bm  = blockIdx.x * 64;
    const int sel = blockIdx.y >> 1;        // 0=Q 1=K 2=V
    const int bn  = (blockIdx.y & 1) * 64;  // column half within the 128-wide matrix

    const float* W    = (sel == 0) ? Wq : (sel == 1 ? Wk : Wv);
    const float* bias = (sel == 0) ? bq : (sel == 1 ? bk : bv);
    float* Out        = (sel == 0) ? g_q : (sel == 1 ? g_k : g_v);

    const int tx = tid & 15;   // col group
    const int ty = tid >> 4;   // row group

    float acc[4][4];
#pragma unroll
    for (int i = 0; i < 4; i++)
#pragma unroll
        for (int j = 0; j < 4; j++) acc[i][j] = 0.f;

    for (int kk = 0; kk < 128; kk += 64) {
        // load A tile (64 rows x 64 k), transpose into k-major smem
#pragma unroll
        for (int j = 0; j < 4; j++) {
            int i   = tid + j * 256;
            int row = i >> 4;
            int kc  = (i & 15) << 2;
            float4 a = make_float4(0.f, 0.f, 0.f, 0.f);
            if (bm + row < n)
                a = *(const float4*)(x + (size_t)(bm + row) * 128 + kk + kc);
            As[kc + 0][row] = a.x;
            As[kc + 1][row] = a.y;
            As[kc + 2][row] = a.z;
            As[kc + 3][row] = a.w;
        }
        // load B tile (64 k x 64 cols)
#pragma unroll
        for (int j = 0; j < 4; j++) {
            int i  = tid + j * 256;
            int k  = i >> 4;
            int cc = (i & 15) << 2;
            *(float4*)&Bs[k][cc] = *(const float4*)(W + (size_t)(kk + k) * 128 + bn + cc);
        }
        __syncthreads();

#pragma unroll 8
        for (int k = 0; k < 64; k++) {
            float a0 = As[k][ty * 4 + 0];
            float a1 = As[k][ty * 4 + 1];
            float a2 = As[k][ty * 4 + 2];
            float a3 = As[k][ty * 4 + 3];
            float4 b = *(const float4*)&Bs[k][tx * 4];
            acc[0][0] += a0 * b.x; acc[0][1] += a0 * b.y; acc[0][2] += a0 * b.z; acc[0][3] += a0 * b.w;
            acc[1][0] += a1 * b.x; acc[1][1] += a1 * b.y; acc[1][2] += a1 * b.z; acc[1][3] += a1 * b.w;
            acc[2][0] += a2 * b.x; acc[2][1] += a2 * b.y; acc[2][2] += a2 * b.z; acc[2][3] += a2 * b.w;
            acc[3][0] += a3 * b.x; acc[3][1] += a3 * b.y; acc[3][2] += a3 * b.z; acc[3][3] += a3 * b.w;
        }
        __syncthreads();
    }

    float4 bb = *(const float4*)(bias + bn + tx * 4);
#pragma unroll
    for (int i = 0; i < 4; i++) {
        int row = bm + ty * 4 + i;
        if (row < n) {
            float4 o;
            o.x = acc[i][0] + bb.x;
            o.y = acc[i][1] + bb.y;
            o.z = acc[i][2] + bb.z;
            o.w = acc[i][3] + bb.w;
            *(float4*)(Out + (size_t)row * 128 + bn + tx * 4) = o;
        }
    }
}

// ---------------- fused pass A: scores + exp + segment sum (warp per edge) ----------------
// No segment-max needed: attn = exp(s)/sum exp(s) is shift-invariant, and scores
// are bounded (|raw/4| <~ 8, mix <= ~1), so plain fp32 exp cannot overflow.
// exp(raw + log(clip(mix))) == exp(raw) * clip(mix)  -> no logf at all.
__global__ __launch_bounds__(256) void edge_fused_kernel(
    const float* __restrict__ pi, const float* __restrict__ vw,
    const int* __restrict__ src, const int* __restrict__ dst,
    float* __restrict__ attn_out, int E)
{
    int warp = (int)((blockIdx.x * (unsigned)blockDim.x + threadIdx.x) >> 5);
    int lane = threadIdx.x & 31;
    if (warp >= E) return;
    int s = src[warp];
    int d = dst[warp];

    float4 q4 = *(const float4*)(g_q + (size_t)d * 128 + lane * 4);
    float4 k4 = *(const float4*)(g_k + (size_t)s * 128 + lane * 4);
    float p = q4.x * k4.x + q4.y * k4.y + q4.z * k4.z + q4.w * k4.w;
    p += __shfl_xor_sync(0xffffffffu, p, 1);
    p += __shfl_xor_sync(0xffffffffu, p, 2);
    // lanes 4h..4h+3 all hold raw dot for head h = lane>>2

    float ex = 0.f;
    if ((lane & 3) == 0) {
        int h = lane >> 2;
        float mix = 0.f;
#pragma unroll
        for (int m = 0; m < 3; m++)
            mix += pi[(size_t)d * 24 + h * 3 + m] * vw[(size_t)warp * 3 + m];
        if (mix > 0.f)
            ex = __expf(p * 0.25f) * fmaxf(mix, 1e-8f);
    }

    // gather heads 0-3 to lane 0, heads 4-7 to lane 16
    int base = lane & 16;
    float e0 = __shfl_sync(0xffffffffu, ex, base + 0);
    float e1 = __shfl_sync(0xffffffffu, ex, base + 4);
    float e2 = __shfl_sync(0xffffffffu, ex, base + 8);
    float e3 = __shfl_sync(0xffffffffu, ex, base + 12);
    if ((lane & 15) == 0) {
        int off = (lane >> 4) * 4;
        float4 v = make_float4(e0, e1, e2, e3);
        *(float4*)(attn_out + (size_t)warp * 8 + off) = v;
        float* sp = g_ssum + (size_t)d * 8 + off;
        asm volatile("red.global.add.v4.f32 [%0], {%1, %2, %3, %4};"
                     :: "l"(sp), "f"(e0), "f"(e1), "f"(e2), "f"(e3)
                     : "memory");
    }
}

// ---------------- pass B: normalize attn + weighted scatter of V (warp per edge) ----------------
__global__ __launch_bounds__(256) void edge_aggregate_kernel(
    const int* __restrict__ src, const int* __restrict__ dst,
    float* __restrict__ attn, float* __restrict__ node_out, int E)
{
    int warp = (int)((blockIdx.x * (unsigned)blockDim.x + threadIdx.x) >> 5);
    int lane = threadIdx.x & 31;
    if (warp >= E) return;
    int s = src[warp];
    int d = dst[warp];

    float a = 0.f;
    if (lane < 8) {
        float ex = attn[(size_t)warp * 8 + lane];
        float ss = g_ssum[(size_t)d * 8 + lane];
        a = ex / fmaxf(ss, 1e-8f);
        attn[(size_t)warp * 8 + lane] = a;
    }
    // lane l needs attn of head l>>2, held by lane (l>>2)
    float ah = __shfl_sync(0xffffffffu, a, lane >> 2);

    float4 v4 = *(const float4*)(g_v + (size_t)s * 128 + lane * 4);
    float* dp = node_out + (size_t)d * 128 + lane * 4;
    asm volatile("red.global.add.v4.f32 [%0], {%1, %2, %3, %4};"
                 :: "l"(dp), "f"(v4.x * ah), "f"(v4.y * ah), "f"(v4.z * ah), "f"(v4.w * ah)
                 : "memory");
}

// ---------------- launch ----------------
extern "C" void kernel_launch(void* const* d_in, const int* in_sizes, int n_in,
                              void* d_out, int out_size)
{
    const float* x  = (const float*)d_in[0];
    const float* pi = (const float*)d_in[1];
    const float* vw = (const float*)d_in[2];
    const float* Wq = (const float*)d_in[3];
    const float* bq = (const float*)d_in[4];
    const float* Wk = (const float*)d_in[5];
    const float* bk = (const float*)d_in[6];
    const float* Wv = (const float*)d_in[7];
    const float* bv = (const float*)d_in[8];
    const int* src  = (const int*)d_in[9];
    const int* dst  = (const int*)d_in[10];

    int n = in_sizes[0] / D_MODEL;
    int E = in_sizes[9];

    float* out_ns   = (float*)d_out;                    // [n, H, DH] = [n,128]
    float* out_attn = out_ns + (size_t)n * D_MODEL;     // [E, H]

    init_kernel<<<(n * D_MODEL + 255) / 256, 256>>>(out_ns, n);
    qkv_gemm_kernel<<<dim3((n + 63) / 64, 6), 256>>>(x, Wq, bq, Wk, bk, Wv, bv, n);
    edge_fused_kernel<<<(E + 7) / 8, 256>>>(pi, vw, src, dst, out_attn, E);
    edge_aggregate_kernel<<<(E + 7) / 8, 256>>>(src, dst, out_attn, out_ns, E);
}

// round 10
// speedup vs baseline: 1.6622x; 1.1832x over previous
#include <cuda_runtime.h>
#include <cstdint>

#define N_NODES  100000
#define D_MODEL  128
#define N_EDGES  1600000
#define HEADS    8
#define DHEAD    16

// ---------------- device scratch (no allocations allowed) ----------------
__device__ float g_q[N_NODES * D_MODEL];
__device__ float g_k[N_NODES * D_MODEL];
__device__ float g_v[N_NODES * D_MODEL];
__device__ float g_ssum[N_NODES * HEADS];

// ---------------- init: zero node accumulator + ssum ----------------
__global__ void init_kernel(float* __restrict__ node_out, int n) {
    int idx = blockIdx.x * blockDim.x + threadIdx.x;
    if (idx < n * D_MODEL) node_out[idx] = 0.f;
    if (idx < n * HEADS)   g_ssum[idx] = 0.f;
}

// ---------------- fused QKV GEMM: C[n,384] = x[n,128] @ [Wq|Wk|Wv] + bias ----------------
__global__ __launch_bounds__(256) void qkv_gemm_kernel(
    const float* __restrict__ x,
    const float* __restrict__ Wq, const float* __restrict__ bq,
    const float* __restrict__ Wk, const float* __restrict__ bk,
    const float* __restrict__ Wv, const float* __restrict__ bv,
    int n)
{
    __shared__ float As[64][65];
    __shared__ float Bs[64][64];

    const int tid = threadIdx.x;
    const int bm  = blockIdx.x * 64;
    const int sel = blockIdx.y >> 1;
    const int bn  = (blockIdx.y & 1) * 64;

    const float* W    = (sel == 0) ? Wq : (sel == 1 ? Wk : Wv);
    const float* bias = (sel == 0) ? bq : (sel == 1 ? bk : bv);
    float* Out        = (sel == 0) ? g_q : (sel == 1 ? g_k : g_v);

    const int tx = tid & 15;
    const int ty = tid >> 4;

    float acc[4][4];
#pragma unroll
    for (int i = 0; i < 4; i++)
#pragma unroll
        for (int j = 0; j < 4; j++) acc[i][j] = 0.f;

    for (int kk = 0; kk < 128; kk += 64) {
#pragma unroll
        for (int j = 0; j < 4; j++) {
            int i   = tid + j * 256;
            int row = i >> 4;
            int kc  = (i & 15) << 2;
            float4 a = make_float4(0.f, 0.f, 0.f, 0.f);
            if (bm + row < n)
                a = *(const float4*)(x + (size_t)(bm + row) * 128 + kk + kc);
            As[kc + 0][row] = a.x;
            As[kc + 1][row] = a.y;
            As[kc + 2][row] = a.z;
            As[kc + 3][row] = a.w;
        }
#pragma unroll
        for (int j = 0; j < 4; j++) {
            int i  = tid + j * 256;
            int k  = i >> 4;
            int cc = (i & 15) << 2;
            *(float4*)&Bs[k][cc] = *(const float4*)(W + (size_t)(kk + k) * 128 + bn + cc);
        }
        __syncthreads();

#pragma unroll 8
        for (int k = 0; k < 64; k++) {
            float a0 = As[k][ty * 4 + 0];
            float a1 = As[k][ty * 4 + 1];
            float a2 = As[k][ty * 4 + 2];
            float a3 = As[k][ty * 4 + 3];
            float4 b = *(const float4*)&Bs[k][tx * 4];
            acc[0][0] += a0 * b.x; acc[0][1] += a0 * b.y; acc[0][2] += a0 * b.z; acc[0][3] += a0 * b.w;
            acc[1][0] += a1 * b.x; acc[1][1] += a1 * b.y; acc[1][2] += a1 * b.z; acc[1][3] += a1 * b.w;
            acc[2][0] += a2 * b.x; acc[2][1] += a2 * b.y; acc[2][2] += a2 * b.z; acc[2][3] += a2 * b.w;
            acc[3][0] += a3 * b.x; acc[3][1] += a3 * b.y; acc[3][2] += a3 * b.z; acc[3][3] += a3 * b.w;
        }
        __syncthreads();
    }

    float4 bb = *(const float4*)(bias + bn + tx * 4);
#pragma unroll
    for (int i = 0; i < 4; i++) {
        int row = bm + ty * 4 + i;
        if (row < n) {
            float4 o;
            o.x = acc[i][0] + bb.x;
            o.y = acc[i][1] + bb.y;
            o.z = acc[i][2] + bb.z;
            o.w = acc[i][3] + bb.w;
            *(float4*)(Out + (size_t)row * 128 + bn + tx * 4) = o;
        }
    }
}

// ---------------- single fused edge sweep (warp per edge) ----------------
// ex = exp(q.k/4) * clip(mix);  attn_out <- ex (unnormalized)
// ssum[dst,h]      += ex          (REDG v4)
// node_out[dst,:]  += ex * v[src] (REDG v4)   -- normalization divided out later
__global__ __launch_bounds__(256) void edge_fused_kernel(
    const float* __restrict__ pi, const float* __restrict__ vw,
    const int* __restrict__ src, const int* __restrict__ dst,
    float* __restrict__ attn_out, float* __restrict__ node_out, int E)
{
    int warp = (int)((blockIdx.x * (unsigned)blockDim.x + threadIdx.x) >> 5);
    int lane = threadIdx.x & 31;
    if (warp >= E) return;
    int s = src[warp];
    int d = dst[warp];

    // issue all three gathers up front for MLP
    float4 q4 = *(const float4*)(g_q + (size_t)d * 128 + lane * 4);
    float4 k4 = *(const float4*)(g_k + (size_t)s * 128 + lane * 4);
    float4 v4 = *(const float4*)(g_v + (size_t)s * 128 + lane * 4);

    float p = q4.x * k4.x + q4.y * k4.y + q4.z * k4.z + q4.w * k4.w;
    p += __shfl_xor_sync(0xffffffffu, p, 1);
    p += __shfl_xor_sync(0xffffffffu, p, 2);
    // lanes 4h..4h+3 all hold raw dot for head h = lane>>2

    float ex = 0.f;
    if ((lane & 3) == 0) {
        int h = lane >> 2;
        float mix = 0.f;
#pragma unroll
        for (int m = 0; m < 3; m++)
            mix += pi[(size_t)d * 24 + h * 3 + m] * vw[(size_t)warp * 3 + m];
        if (mix > 0.f)
            ex = __expf(p * 0.25f) * fmaxf(mix, 1e-8f);
    }

    // every lane grabs its head's ex (held on lane (lane>>2)*4 == lane & ~3)
    float ah = __shfl_sync(0xffffffffu, ex, lane & 0x1C);

    // store unnormalized attn + accumulate ssum (heads 0-3 via lane0, 4-7 via lane16)
    int base = lane & 16;
    float e0 = __shfl_sync(0xffffffffu, ex, base + 0);
    float e1 = __shfl_sync(0xffffffffu, ex, base + 4);
    float e2 = __shfl_sync(0xffffffffu, ex, base + 8);
    float e3 = __shfl_sync(0xffffffffu, ex, base + 12);
    if ((lane & 15) == 0) {
        int off = (lane >> 4) * 4;
        *(float4*)(attn_out + (size_t)warp * 8 + off) = make_float4(e0, e1, e2, e3);
        float* sp = g_ssum + (size_t)d * 8 + off;
        asm volatile("red.global.add.v4.f32 [%0], {%1, %2, %3, %4};"
                     :: "l"(sp), "f"(e0), "f"(e1), "f"(e2), "f"(e3)
                     : "memory");
    }

    // scatter ex * v[src] into node accumulator
    float* dp = node_out + (size_t)d * 128 + lane * 4;
    asm volatile("red.global.add.v4.f32 [%0], {%1, %2, %3, %4};"
                 :: "l"(dp), "f"(v4.x * ah), "f"(v4.y * ah), "f"(v4.z * ah), "f"(v4.w * ah)
                 : "memory");
}

// ---------------- epilogue 1: node_out /= max(ssum, 1e-8)  (float4 per thread) ----------------
__global__ void node_norm_kernel(float* __restrict__ node_out, int n) {
    int idx = blockIdx.x * blockDim.x + threadIdx.x;   // over n*32 float4s
    if (idx >= n * 32) return;
    int node = idx >> 5;
    int h    = (idx >> 2) & 7;
    float ss = g_ssum[(size_t)node * 8 + h];
    float inv = 1.f / fmaxf(ss, 1e-8f);
    float4 v = *(float4*)(node_out + (size_t)idx * 4);
    v.x *= inv; v.y *= inv; v.z *= inv; v.w *= inv;
    *(float4*)(node_out + (size_t)idx * 4) = v;
}

// ---------------- epilogue 2: attn[e,h] = ex / max(ssum[dst,h],1e-8) (thread per edge) ----------------
__global__ void attn_norm_kernel(const int* __restrict__ dst,
                                 float* __restrict__ attn, int E) {
    int e = blockIdx.x * blockDim.x + threadIdx.x;
    if (e >= E) return;
    int d = dst[e];
    float4 s0 = *(const float4*)(g_ssum + (size_t)d * 8);
    float4 s1 = *(const float4*)(g_ssum + (size_t)d * 8 + 4);
    float4 a0 = *(float4*)(attn + (size_t)e * 8);
    float4 a1 = *(float4*)(attn + (size_t)e * 8 + 4);
    a0.x /= fmaxf(s0.x, 1e-8f); a0.y /= fmaxf(s0.y, 1e-8f);
    a0.z /= fmaxf(s0.z, 1e-8f); a0.w /= fmaxf(s0.w, 1e-8f);
    a1.x /= fmaxf(s1.x, 1e-8f); a1.y /= fmaxf(s1.y, 1e-8f);
    a1.z /= fmaxf(s1.z, 1e-8f); a1.w /= fmaxf(s1.w, 1e-8f);
    *(float4*)(attn + (size_t)e * 8)     = a0;
    *(float4*)(attn + (size_t)e * 8 + 4) = a1;
}

// ---------------- launch ----------------
extern "C" void kernel_launch(void* const* d_in, const int* in_sizes, int n_in,
                              void* d_out, int out_size)
{
    const float* x  = (const float*)d_in[0];
    const float* pi = (const float*)d_in[1];
    const float* vw = (const float*)d_in[2];
    const float* Wq = (const float*)d_in[3];
    const float* bq = (const float*)d_in[4];
    const float* Wk = (const float*)d_in[5];
    const float* bk = (const float*)d_in[6];
    const float* Wv = (const float*)d_in[7];
    const float* bv = (const float*)d_in[8];
    const int* src  = (const int*)d_in[9];
    const int* dst  = (const int*)d_in[10];

    int n = in_sizes[0] / D_MODEL;
    int E = in_sizes[9];

    float* out_ns   = (float*)d_out;                    // [n, H, DH] = [n,128]
    float* out_attn = out_ns + (size_t)n * D_MODEL;     // [E, H]

    init_kernel<<<(n * D_MODEL + 255) / 256, 256>>>(out_ns, n);
    qkv_gemm_kernel<<<dim3((n + 63) / 64, 6), 256>>>(x, Wq, bq, Wk, bk, Wv, bv, n);
    edge_fused_kernel<<<(E + 7) / 8, 256>>>(pi, vw, src, dst, out_attn, out_ns, E);
    node_norm_kernel<<<(n * 32 + 255) / 256, 256>>>(out_ns, n);
    attn_norm_kernel<<<(E + 255) / 256, 256>>>(dst, out_attn, E);
}